// round 15
// baseline (speedup 1.0000x reference)
#include <cuda_runtime.h>
#include <cuda_fp16.h>
#include <stdint.h>
#include <math.h>

#define T    512
#define H    2048
#define II   1024
#define E    64
#define KSEL 8

#define BM   128
#define BK   32
#define PADK 40                      // fp16 elems per row slot: 80B, ldmatrix conflict-free

// stage = 7680 fp16 elems = 15360 B; two stages.
#define STG_ELEMS 7680
#define META_OFF  (2 * STG_ELEMS * 2)          // 30720 B
#define SMEM_DYN  (META_OFF + 1536)

// gateup regions (elem offsets within a stage): A 128x40, G 32x40, U 32x40
#define GA 0
#define GG 5120
#define GU 6400
// down regions: A 128x40, B 64x40
#define DA 0
#define DB 5120

// -------- device-global scratch (no allocations allowed) --------
__device__ int    g_cnt[E];
__device__ int    g_off[E];
__device__ int    g_tok[E * T];
__device__ float  g_prob[E * T];
__device__ __half g_act[(size_t)T * KSEL * II];   // activations fp16
__device__ __half g_xh[(size_t)T * H];            // x pre-converted fp16

// ======================= helpers =======================
__device__ __forceinline__ uint32_t smem_u32(const void* p) {
    uint32_t a;
    asm("{ .reg .u64 t; cvta.to.shared.u64 t, %1; cvt.u32.u64 %0, t; }" : "=r"(a) : "l"(p));
    return a;
}

__device__ __forceinline__ void ldm_x4(uint32_t r[4], uint32_t addr) {
    asm volatile("ldmatrix.sync.aligned.m8n8.x4.shared.b16 {%0,%1,%2,%3}, [%4];"
                 : "=r"(r[0]), "=r"(r[1]), "=r"(r[2]), "=r"(r[3]) : "r"(addr));
}
__device__ __forceinline__ void mma_f16(float d[4], const uint32_t a[4], uint32_t b0, uint32_t b1) {
    asm volatile("mma.sync.aligned.m16n8k16.row.col.f32.f16.f16.f32 "
                 "{%0,%1,%2,%3}, {%4,%5,%6,%7}, {%8,%9}, {%0,%1,%2,%3};"
                 : "+f"(d[0]), "+f"(d[1]), "+f"(d[2]), "+f"(d[3])
                 : "r"(a[0]), "r"(a[1]), "r"(a[2]), "r"(a[3]), "r"(b0), "r"(b1));
}
// fp32x4 -> fp16x4 (8 B)
__device__ __forceinline__ uint2 cvt4_f16(float4 v) {
    __half2 a = __floats2half2_rn(v.x, v.y);
    __half2 b = __floats2half2_rn(v.z, v.w);
    uint2 r;
    r.x = *(uint32_t*)&a;
    r.y = *(uint32_t*)&b;
    return r;
}

// ======================= x -> fp16 =======================
__global__ void xhalf_kernel(const float* __restrict__ x)
{
    const int i = blockIdx.x * 256 + threadIdx.x;    // over T*H/4
    float4 v = ((const float4*)x)[i];
    ((uint2*)g_xh)[i] = cvt4_f16(v);
}

// ======================= gating =======================
__global__ void gate_kernel(const float* __restrict__ x,
                            const float* __restrict__ Wgate)
{
    __shared__ float sx[H];
    __shared__ float slog[E];
    __shared__ int   s_ids[KSEL];
    __shared__ float s_p[KSEL];

    const int t = blockIdx.x, tid = threadIdx.x;
    for (int i = tid; i < H; i += blockDim.x) sx[i] = x[(size_t)t * H + i];
    __syncthreads();

    const int w = tid >> 5, lane = tid & 31;
    for (int j = 0; j < 8; j++) {
        const int e = w * 8 + j;
        const float* wr = Wgate + (size_t)e * H;
        float s = 0.f;
        for (int h = lane; h < H; h += 32) s += sx[h] * wr[h];
        #pragma unroll
        for (int o = 16; o > 0; o >>= 1) s += __shfl_xor_sync(0xffffffffu, s, o);
        if (lane == 0) slog[e] = s;
    }
    __syncthreads();

    if (tid == 0) {
        float vals[KSEL]; int ids[KSEL];
        for (int j = 0; j < KSEL; j++) {
            float best = -1e30f; int bi = 0;
            for (int e = 0; e < E; e++)
                if (slog[e] > best) { best = slog[e]; bi = e; }
            vals[j] = best; ids[j] = bi; slog[bi] = -1e30f;
        }
        const float m = vals[0];
        float sum = 0.f;
        for (int j = 0; j < KSEL; j++) { vals[j] = expf(vals[j] - m); sum += vals[j]; }
        const float inv = 1.f / sum;
        for (int j = 0; j < KSEL; j++) { s_ids[j] = ids[j]; s_p[j] = vals[j] * inv; }
    }
    __syncthreads();

    if (tid < KSEL) {
        const int e = s_ids[tid];
        const int pos = atomicAdd(&g_cnt[e], 1);
        g_tok[e * T + pos]  = t;
        g_prob[e * T + pos] = s_p[tid];
    }
}

__global__ void scan_kernel()
{
    if (threadIdx.x == 0) {
        int s = 0;
        for (int e = 0; e < E; e++) { g_off[e] = s; s += g_cnt[e]; }
    }
}

// ======================= gate/up: fp16 mma + SwiGLU =======================
// CTA: 128 tokens x 32 i x {Wg,Wu}. 8 warps 4m x 2n, warp 32m x 16i x 2 mats.
__global__ __launch_bounds__(256, 2) void gateup_mma(const float* __restrict__ Wg,
                                                     const float* __restrict__ Wu)
{
    extern __shared__ __align__(16) char smraw[];
    __half* sm = (__half*)smraw;

    const int e   = blockIdx.z;
    const int cnt = g_cnt[e];
    const int m0  = blockIdx.y * BM;
    if (m0 >= cnt) return;
    const int i0   = blockIdx.x * 32;
    const int base = g_off[e];
    const int tid = threadIdx.x, wid = tid >> 5, lane = tid & 31;

    int*   stok = (int*)(smraw + META_OFF);
    float* sp   = (float*)(smraw + META_OFF + 512);
    if (tid < BM) {
        const int mm = min(m0 + tid, cnt - 1);
        stok[tid] = g_tok[e * T + mm];
        sp[tid]   = (m0 + tid < cnt) ? g_prob[e * T + m0 + tid] : 0.f;
    }
    __syncthreads();

    const float* WgE = Wg + ((size_t)e * II + i0) * H;
    const float* WuE = Wu + ((size_t)e * II + i0) * H;
    const int NCH = H / BK;    // 64

    // ---- producer geometry ----
    // A (fp16): 128 rows x 4 segs of 8 elems = 512 tasks, 2/thread
    const __half* srcA[2];
    int aoff[2];
    #pragma unroll
    for (int j = 0; j < 2; j++) {
        const int idx = tid + j * 256, ra = idx >> 2, sg = idx & 3;
        srcA[j] = g_xh + (size_t)stok[ra] * H + sg * 8;
        aoff[j] = ra * PADK + sg * 8;
    }
    // B (fp32): G,U each 32 rows x 8 float4 segs = 256 tasks, 1/thread
    const int rb = tid >> 3, cb = tid & 7;
    const float* srcG = WgE + (size_t)rb * H + cb * 4;
    const float* srcU = WuE + (size_t)rb * H + cb * 4;
    const int boff = rb * PADK + cb * 4;

    const int wm = wid >> 1;   // 0..3
    const int wn = wid & 1;    // 0..1
    const uint32_t offA0 = (uint32_t)((wm * 32 + (lane & 15)) * PADK + ((lane >> 4) << 3));
    const uint32_t offA1 = offA0 + 16 * PADK;
    const uint32_t offB  = (uint32_t)((wn * 16 + ((lane >> 4) << 3) + (lane & 7)) * PADK
                                      + (((lane >> 3) & 1) << 3));

    float ag[2][2][4] = {}, au[2][2][4] = {};
    uint4  pa[2];
    float4 pg, pu;

    // prefetch + fill stage 0
    {
        #pragma unroll
        for (int j = 0; j < 2; j++) pa[j] = *(const uint4*)srcA[j];
        pg = *(const float4*)srcG;
        pu = *(const float4*)srcU;
        #pragma unroll
        for (int j = 0; j < 2; j++) *(uint4*)(sm + GA + aoff[j]) = pa[j];
        *(uint2*)(sm + GG + boff) = cvt4_f16(pg);
        *(uint2*)(sm + GU + boff) = cvt4_f16(pu);
        __syncthreads();
    }

    for (int ch = 0; ch < NCH; ch++) {
        if (ch + 1 < NCH) {
            const int k0 = (ch + 1) * BK;
            #pragma unroll
            for (int j = 0; j < 2; j++) pa[j] = *(const uint4*)(srcA[j] + k0);
            pg = *(const float4*)(srcG + k0);
            pu = *(const float4*)(srcU + k0);
        }

        // compute on stage ch&1
        {
            const uint32_t sbase = smem_u32(sm + (ch & 1) * STG_ELEMS);
            #pragma unroll
            for (int k16 = 0; k16 < BK; k16 += 16) {
                const uint32_t kb = (uint32_t)k16 * 2;
                uint32_t ah[2][4];
                ldm_x4(ah[0], sbase + (GA * 2) + (offA0 * 2) + kb);
                ldm_x4(ah[1], sbase + (GA * 2) + (offA1 * 2) + kb);
                uint32_t gv[4], uv[4];
                ldm_x4(gv, sbase + (GG * 2) + (offB * 2) + kb);
                ldm_x4(uv, sbase + (GU * 2) + (offB * 2) + kb);
                #pragma unroll
                for (int mt = 0; mt < 2; mt++) {
                    #pragma unroll
                    for (int it = 0; it < 2; it++) {
                        mma_f16(ag[mt][it], ah[mt], gv[it * 2], gv[it * 2 + 1]);
                        mma_f16(au[mt][it], ah[mt], uv[it * 2], uv[it * 2 + 1]);
                    }
                }
            }
        }

        if (ch + 1 < NCH) {
            __half* s = sm + ((ch + 1) & 1) * STG_ELEMS;
            #pragma unroll
            for (int j = 0; j < 2; j++) *(uint4*)(s + GA + aoff[j]) = pa[j];
            *(uint2*)(s + GG + boff) = cvt4_f16(pg);
            *(uint2*)(s + GU + boff) = cvt4_f16(pu);
        }
        __syncthreads();
    }

    // epilogue: silu(hg)*hu*p -> g_act (fp16)
    #pragma unroll
    for (int mt = 0; mt < 2; mt++) {
        #pragma unroll
        for (int it = 0; it < 2; it++) {
            const int c  = i0 + wn * 16 + it * 8 + (lane & 3) * 2;
            const int r0 = wm * 32 + mt * 16 + (lane >> 2);
            #pragma unroll
            for (int hf = 0; hf < 2; hf++) {
                const int r = r0 + hf * 8;
                if (m0 + r < cnt) {
                    const float p = sp[r];
                    const float hg0 = ag[mt][it][hf * 2 + 0], hu0 = au[mt][it][hf * 2 + 0];
                    const float hg1 = ag[mt][it][hf * 2 + 1], hu1 = au[mt][it][hf * 2 + 1];
                    const float v0 = hg0 / (1.f + expf(-hg0)) * hu0 * p;
                    const float v1 = hg1 / (1.f + expf(-hg1)) * hu1 * p;
                    __half2 hv = __floats2half2_rn(v0, v1);
                    *(uint32_t*)(g_act + (size_t)(base + m0 + r) * II + c) = *(uint32_t*)&hv;
                }
            }
        }
    }
}

// ======================= down: fp16 mma + scatter =======================
// CTA: 128 rows x 64 h-cols. 8 warps 4m x 2n, warp 32m x 32n.
__global__ __launch_bounds__(256, 2) void down_mma(const float* __restrict__ Wd,
                                                   float* __restrict__ out)
{
    extern __shared__ __align__(16) char smraw[];
    __half* sm = (__half*)smraw;

    const int e   = blockIdx.z;
    const int cnt = g_cnt[e];
    const int m0  = blockIdx.y * BM;
    if (m0 >= cnt) return;
    const int n0   = blockIdx.x * 64;
    const int base = g_off[e];
    const int tid = threadIdx.x, wid = tid >> 5, lane = tid & 31;

    int* stok = (int*)(smraw + META_OFF);
    int* srow = (int*)(smraw + META_OFF + 512);
    if (tid < BM) {
        const int mm = min(m0 + tid, cnt - 1);
        stok[tid] = g_tok[e * T + mm];
        srow[tid] = base + mm;
    }
    __syncthreads();

    const float* WdE = Wd + ((size_t)e * H + n0) * II;
    const int NCH = II / BK;   // 32

    // ---- producer geometry ----
    // A (fp16): 128 rows x 4 segs = 512 tasks, 2/thread
    const __half* srcA[2];
    int aoff[2];
    #pragma unroll
    for (int j = 0; j < 2; j++) {
        const int idx = tid + j * 256, ra = idx >> 2, sg = idx & 3;
        srcA[j] = g_act + (size_t)srow[ra] * II + sg * 8;
        aoff[j] = ra * PADK + sg * 8;
    }
    // B (fp32): 64 rows x 8 float4 segs = 512 tasks, 2/thread
    const float* srcB[2];
    int boff[2];
    #pragma unroll
    for (int j = 0; j < 2; j++) {
        const int idx = tid + j * 256, r = idx >> 3, c = idx & 7;
        srcB[j] = WdE + (size_t)r * II + c * 4;
        boff[j] = r * PADK + c * 4;
    }

    const int wm = wid >> 1;   // 0..3
    const int wn = wid & 1;    // 0..1
    const uint32_t offA0 = (uint32_t)((wm * 32 + (lane & 15)) * PADK + ((lane >> 4) << 3));
    const uint32_t offA1 = offA0 + 16 * PADK;
    const uint32_t offB0 = (uint32_t)((wn * 32 + ((lane >> 4) << 3) + (lane & 7)) * PADK
                                      + (((lane >> 3) & 1) << 3));
    const uint32_t offB1 = offB0 + 16 * PADK;

    float acc[2][4][4] = {};
    uint4  pa[2];
    float4 pb[2];

    {
        #pragma unroll
        for (int j = 0; j < 2; j++) pa[j] = *(const uint4*)srcA[j];
        #pragma unroll
        for (int j = 0; j < 2; j++) pb[j] = *(const float4*)srcB[j];
        #pragma unroll
        for (int j = 0; j < 2; j++) *(uint4*)(sm + DA + aoff[j]) = pa[j];
        #pragma unroll
        for (int j = 0; j < 2; j++) *(uint2*)(sm + DB + boff[j]) = cvt4_f16(pb[j]);
        __syncthreads();
    }

    for (int ch = 0; ch < NCH; ch++) {
        if (ch + 1 < NCH) {
            const int k0 = (ch + 1) * BK;
            #pragma unroll
            for (int j = 0; j < 2; j++) pa[j] = *(const uint4*)(srcA[j] + k0);
            #pragma unroll
            for (int j = 0; j < 2; j++) pb[j] = *(const float4*)(srcB[j] + k0);
        }

        {
            const uint32_t sbase = smem_u32(sm + (ch & 1) * STG_ELEMS);
            #pragma unroll
            for (int k16 = 0; k16 < BK; k16 += 16) {
                const uint32_t kb = (uint32_t)k16 * 2;
                uint32_t ah[2][4];
                ldm_x4(ah[0], sbase + (DA * 2) + (offA0 * 2) + kb);
                ldm_x4(ah[1], sbase + (DA * 2) + (offA1 * 2) + kb);
                uint32_t bv[2][4];
                ldm_x4(bv[0], sbase + (DB * 2) + (offB0 * 2) + kb);
                ldm_x4(bv[1], sbase + (DB * 2) + (offB1 * 2) + kb);
                #pragma unroll
                for (int mt = 0; mt < 2; mt++) {
                    #pragma unroll
                    for (int nt = 0; nt < 4; nt++) {
                        const int p = nt >> 1, q = (nt & 1) * 2;
                        mma_f16(acc[mt][nt], ah[mt], bv[p][q], bv[p][q + 1]);
                    }
                }
            }
        }

        if (ch + 1 < NCH) {
            __half* s = sm + ((ch + 1) & 1) * STG_ELEMS;
            #pragma unroll
            for (int j = 0; j < 2; j++) *(uint4*)(s + DA + aoff[j]) = pa[j];
            #pragma unroll
            for (int j = 0; j < 2; j++) *(uint2*)(s + DB + boff[j]) = cvt4_f16(pb[j]);
        }
        __syncthreads();
    }

    // epilogue: atomic scatter into out
    #pragma unroll
    for (int mt = 0; mt < 2; mt++) {
        #pragma unroll
        for (int nt = 0; nt < 4; nt++) {
            const int c  = n0 + wn * 32 + nt * 8 + (lane & 3) * 2;
            const int r0 = wm * 32 + mt * 16 + (lane >> 2);
            #pragma unroll
            for (int hf = 0; hf < 2; hf++) {
                const int r = r0 + hf * 8;
                if (m0 + r < cnt) {
                    float* orow = out + (size_t)stok[r] * H + c;
                    atomicAdd(&orow[0], acc[mt][nt][hf * 2 + 0]);
                    atomicAdd(&orow[1], acc[mt][nt][hf * 2 + 1]);
                }
            }
        }
    }
}

// ======================= launch =======================
extern "C" void kernel_launch(void* const* d_in, const int* in_sizes, int n_in,
                              void* d_out, int out_size)
{
    const float* x     = (const float*)d_in[0];
    const float* Wg    = (const float*)d_in[1];
    const float* Wu    = (const float*)d_in[2];
    const float* Wd    = (const float*)d_in[3];
    const float* Wgate = (const float*)d_in[4];
    float* out = (float*)d_out;

    cudaFuncSetAttribute(gateup_mma, cudaFuncAttributeMaxDynamicSharedMemorySize, SMEM_DYN);
    cudaFuncSetAttribute(down_mma,   cudaFuncAttributeMaxDynamicSharedMemorySize, SMEM_DYN);

    void* cnt_ptr = nullptr;
    cudaGetSymbolAddress(&cnt_ptr, g_cnt);
    cudaMemsetAsync(cnt_ptr, 0, E * sizeof(int));
    cudaMemsetAsync(d_out, 0, (size_t)T * H * sizeof(float));

    xhalf_kernel<<<(T * H / 4) / 256, 256>>>(x);
    gate_kernel<<<T, 256>>>(x, Wgate);
    scan_kernel<<<1, 32>>>();

    dim3 g1(II / 32, T / BM, E);     // 32 x 4 x 64
    gateup_mma<<<g1, 256, SMEM_DYN>>>(Wg, Wu);

    dim3 g2(H / 64, T / BM, E);      // 32 x 4 x 64
    down_mma<<<g2, 256, SMEM_DYN>>>(Wd, out);
}

// round 16
// speedup vs baseline: 1.4882x; 1.4882x over previous
#include <cuda_runtime.h>
#include <cuda_fp16.h>
#include <stdint.h>
#include <math.h>

#define T    512
#define H    2048
#define II   1024
#define E    64
#define KSEL 8

#define BM   64
#define BK   64
#define PADK 72                      // fp16 elems per row slot: 144B, ldmatrix conflict-free

// stage = 13824 fp16 elems = 27648 B; two stages.
#define STG_ELEMS 13824
#define META_OFF  (2 * STG_ELEMS * 2)          // 55296 B
#define SMEM_DYN  (META_OFF + 1024)

// gateup regions (elem offsets within a stage): A 64x72, G 64x72, U 64x72
#define GA 0
#define GG 4608
#define GU 9216
// down regions: A 64x72, B 128x72
#define DA 0
#define DB 4608

// -------- device-global scratch (no allocations allowed) --------
__device__ int    g_cnt[E];
__device__ int    g_off[E];
__device__ int    g_tok[E * T];
__device__ float  g_prob[E * T];
__device__ __half g_act[(size_t)T * KSEL * II];   // activations fp16
__device__ __half g_xh[(size_t)T * H];            // x pre-converted fp16

// ======================= helpers =======================
__device__ __forceinline__ uint32_t smem_u32(const void* p) {
    uint32_t a;
    asm("{ .reg .u64 t; cvta.to.shared.u64 t, %1; cvt.u32.u64 %0, t; }" : "=r"(a) : "l"(p));
    return a;
}

__device__ __forceinline__ void ldm_x4(uint32_t r[4], uint32_t addr) {
    asm volatile("ldmatrix.sync.aligned.m8n8.x4.shared.b16 {%0,%1,%2,%3}, [%4];"
                 : "=r"(r[0]), "=r"(r[1]), "=r"(r[2]), "=r"(r[3]) : "r"(addr));
}
__device__ __forceinline__ void mma_f16(float d[4], const uint32_t a[4], uint32_t b0, uint32_t b1) {
    asm volatile("mma.sync.aligned.m16n8k16.row.col.f32.f16.f16.f32 "
                 "{%0,%1,%2,%3}, {%4,%5,%6,%7}, {%8,%9}, {%0,%1,%2,%3};"
                 : "+f"(d[0]), "+f"(d[1]), "+f"(d[2]), "+f"(d[3])
                 : "r"(a[0]), "r"(a[1]), "r"(a[2]), "r"(a[3]), "r"(b0), "r"(b1));
}
// fp32x4 -> fp16x4 (8 B)
__device__ __forceinline__ uint2 cvt4_f16(float4 v) {
    __half2 a = __floats2half2_rn(v.x, v.y);
    __half2 b = __floats2half2_rn(v.z, v.w);
    uint2 r;
    r.x = *(uint32_t*)&a;
    r.y = *(uint32_t*)&b;
    return r;
}

// ======================= x -> fp16 =======================
__global__ void xhalf_kernel(const float* __restrict__ x)
{
    const int i = blockIdx.x * 256 + threadIdx.x;    // over T*H/4
    float4 v = ((const float4*)x)[i];
    ((uint2*)g_xh)[i] = cvt4_f16(v);
}

// ======================= gating =======================
__global__ void gate_kernel(const float* __restrict__ x,
                            const float* __restrict__ Wgate)
{
    __shared__ float sx[H];
    __shared__ float slog[E];
    __shared__ int   s_ids[KSEL];
    __shared__ float s_p[KSEL];

    const int t = blockIdx.x, tid = threadIdx.x;
    for (int i = tid; i < H; i += blockDim.x) sx[i] = x[(size_t)t * H + i];
    __syncthreads();

    const int w = tid >> 5, lane = tid & 31;
    for (int j = 0; j < 8; j++) {
        const int e = w * 8 + j;
        const float* wr = Wgate + (size_t)e * H;
        float s = 0.f;
        for (int h = lane; h < H; h += 32) s += sx[h] * wr[h];
        #pragma unroll
        for (int o = 16; o > 0; o >>= 1) s += __shfl_xor_sync(0xffffffffu, s, o);
        if (lane == 0) slog[e] = s;
    }
    __syncthreads();

    if (tid == 0) {
        float vals[KSEL]; int ids[KSEL];
        for (int j = 0; j < KSEL; j++) {
            float best = -1e30f; int bi = 0;
            for (int e = 0; e < E; e++)
                if (slog[e] > best) { best = slog[e]; bi = e; }
            vals[j] = best; ids[j] = bi; slog[bi] = -1e30f;
        }
        const float m = vals[0];
        float sum = 0.f;
        for (int j = 0; j < KSEL; j++) { vals[j] = expf(vals[j] - m); sum += vals[j]; }
        const float inv = 1.f / sum;
        for (int j = 0; j < KSEL; j++) { s_ids[j] = ids[j]; s_p[j] = vals[j] * inv; }
    }
    __syncthreads();

    if (tid < KSEL) {
        const int e = s_ids[tid];
        const int pos = atomicAdd(&g_cnt[e], 1);
        g_tok[e * T + pos]  = t;
        g_prob[e * T + pos] = s_p[tid];
    }
}

__global__ void scan_kernel()
{
    if (threadIdx.x == 0) {
        int s = 0;
        for (int e = 0; e < E; e++) { g_off[e] = s; s += g_cnt[e]; }
    }
}

// ======================= gate/up: fp16 mma + SwiGLU (BK=64) =======================
// CTA: 64 tokens x 64 i x {Wg,Wu}. 8 warps 2m x 4n, warp 32m x 16i x 2 mats.
__global__ __launch_bounds__(256, 2) void gateup_mma(const float* __restrict__ Wg,
                                                     const float* __restrict__ Wu)
{
    extern __shared__ __align__(16) char smraw[];
    __half* sm = (__half*)smraw;

    const int e   = blockIdx.z;
    const int cnt = g_cnt[e];
    const int m0  = blockIdx.y * BM;
    if (m0 >= cnt) return;
    const int i0   = blockIdx.x * 64;
    const int base = g_off[e];
    const int tid = threadIdx.x, wid = tid >> 5, lane = tid & 31;

    int*   stok = (int*)(smraw + META_OFF);
    float* sp   = (float*)(smraw + META_OFF + 256);
    if (tid < BM) {
        const int mm = min(m0 + tid, cnt - 1);
        stok[tid] = g_tok[e * T + mm];
        sp[tid]   = (m0 + tid < cnt) ? g_prob[e * T + m0 + tid] : 0.f;
    }
    __syncthreads();

    const float* WgE = Wg + ((size_t)e * II + i0) * H;
    const float* WuE = Wu + ((size_t)e * II + i0) * H;
    const int NCH = H / BK;    // 32

    // ---- producer geometry ----
    // A (fp16): 64 rows x 8 segs of 8 elems = 512 tasks, 2/thread
    const __half* srcA[2];
    int aoff[2];
    #pragma unroll
    for (int j = 0; j < 2; j++) {
        const int idx = tid + j * 256, ra = idx >> 3, sg = idx & 7;
        srcA[j] = g_xh + (size_t)stok[ra] * H + sg * 8;
        aoff[j] = ra * PADK + sg * 8;
    }
    // B (fp32): G,U each 64 rows x 16 float4 segs = 1024 tasks, 4/thread
    const float* srcG[4]; const float* srcU[4];
    int boff[4];
    #pragma unroll
    for (int j = 0; j < 4; j++) {
        const int idx = tid + j * 256, r = idx >> 4, c = idx & 15;
        srcG[j] = WgE + (size_t)r * H + c * 4;
        srcU[j] = WuE + (size_t)r * H + c * 4;
        boff[j] = r * PADK + c * 4;
    }

    const int wm = wid >> 2;   // 0..1
    const int wn = wid & 3;    // 0..3
    const uint32_t offA0 = (uint32_t)((wm * 32 + (lane & 15)) * PADK + ((lane >> 4) << 3));
    const uint32_t offA1 = offA0 + 16 * PADK;
    const uint32_t offB  = (uint32_t)((wn * 16 + ((lane >> 4) << 3) + (lane & 7)) * PADK
                                      + (((lane >> 3) & 1) << 3));

    float ag[2][2][4] = {}, au[2][2][4] = {};
    uint4  pa[2];
    float4 pg[4], pu[4];

    // prefetch + fill stage 0
    {
        #pragma unroll
        for (int j = 0; j < 2; j++) pa[j] = *(const uint4*)srcA[j];
        #pragma unroll
        for (int j = 0; j < 4; j++) { pg[j] = *(const float4*)srcG[j]; pu[j] = *(const float4*)srcU[j]; }
        #pragma unroll
        for (int j = 0; j < 2; j++) *(uint4*)(sm + GA + aoff[j]) = pa[j];
        #pragma unroll
        for (int j = 0; j < 4; j++) {
            *(uint2*)(sm + GG + boff[j]) = cvt4_f16(pg[j]);
            *(uint2*)(sm + GU + boff[j]) = cvt4_f16(pu[j]);
        }
        __syncthreads();
    }

    for (int ch = 0; ch < NCH; ch++) {
        if (ch + 1 < NCH) {
            const int k0 = (ch + 1) * BK;
            #pragma unroll
            for (int j = 0; j < 2; j++) pa[j] = *(const uint4*)(srcA[j] + k0);
            #pragma unroll
            for (int j = 0; j < 4; j++) { pg[j] = *(const float4*)(srcG[j] + k0); pu[j] = *(const float4*)(srcU[j] + k0); }
        }

        // compute on stage ch&1
        {
            const uint32_t sbase = smem_u32(sm + (ch & 1) * STG_ELEMS);
            #pragma unroll
            for (int k16 = 0; k16 < BK; k16 += 16) {
                const uint32_t kb = (uint32_t)k16 * 2;
                uint32_t ah[2][4];
                ldm_x4(ah[0], sbase + (GA * 2) + (offA0 * 2) + kb);
                ldm_x4(ah[1], sbase + (GA * 2) + (offA1 * 2) + kb);
                uint32_t gv[4], uv[4];
                ldm_x4(gv, sbase + (GG * 2) + (offB * 2) + kb);
                ldm_x4(uv, sbase + (GU * 2) + (offB * 2) + kb);
                #pragma unroll
                for (int mt = 0; mt < 2; mt++) {
                    #pragma unroll
                    for (int it = 0; it < 2; it++) {
                        mma_f16(ag[mt][it], ah[mt], gv[it * 2], gv[it * 2 + 1]);
                        mma_f16(au[mt][it], ah[mt], uv[it * 2], uv[it * 2 + 1]);
                    }
                }
            }
        }

        if (ch + 1 < NCH) {
            __half* s = sm + ((ch + 1) & 1) * STG_ELEMS;
            #pragma unroll
            for (int j = 0; j < 2; j++) *(uint4*)(s + GA + aoff[j]) = pa[j];
            #pragma unroll
            for (int j = 0; j < 4; j++) {
                *(uint2*)(s + GG + boff[j]) = cvt4_f16(pg[j]);
                *(uint2*)(s + GU + boff[j]) = cvt4_f16(pu[j]);
            }
        }
        __syncthreads();
    }

    // epilogue: silu(hg)*hu*p -> g_act (fp16)
    #pragma unroll
    for (int mt = 0; mt < 2; mt++) {
        #pragma unroll
        for (int it = 0; it < 2; it++) {
            const int c  = i0 + wn * 16 + it * 8 + (lane & 3) * 2;
            const int r0 = wm * 32 + mt * 16 + (lane >> 2);
            #pragma unroll
            for (int hf = 0; hf < 2; hf++) {
                const int r = r0 + hf * 8;
                if (m0 + r < cnt) {
                    const float p = sp[r];
                    const float hg0 = ag[mt][it][hf * 2 + 0], hu0 = au[mt][it][hf * 2 + 0];
                    const float hg1 = ag[mt][it][hf * 2 + 1], hu1 = au[mt][it][hf * 2 + 1];
                    const float v0 = hg0 / (1.f + expf(-hg0)) * hu0 * p;
                    const float v1 = hg1 / (1.f + expf(-hg1)) * hu1 * p;
                    __half2 hv = __floats2half2_rn(v0, v1);
                    *(uint32_t*)(g_act + (size_t)(base + m0 + r) * II + c) = *(uint32_t*)&hv;
                }
            }
        }
    }
}

// ======================= down: fp16 mma + scatter (BK=64) =======================
// CTA: 64 rows x 128 h-cols. 8 warps 2m x 4n, warp 32m x 32n.
__global__ __launch_bounds__(256, 2) void down_mma(const float* __restrict__ Wd,
                                                   float* __restrict__ out)
{
    extern __shared__ __align__(16) char smraw[];
    __half* sm = (__half*)smraw;

    const int e   = blockIdx.z;
    const int cnt = g_cnt[e];
    const int m0  = blockIdx.y * BM;
    if (m0 >= cnt) return;
    const int n0   = blockIdx.x * 128;
    const int base = g_off[e];
    const int tid = threadIdx.x, wid = tid >> 5, lane = tid & 31;

    int* stok = (int*)(smraw + META_OFF);
    int* srow = (int*)(smraw + META_OFF + 256);
    if (tid < BM) {
        const int mm = min(m0 + tid, cnt - 1);
        stok[tid] = g_tok[e * T + mm];
        srow[tid] = base + mm;
    }
    __syncthreads();

    const float* WdE = Wd + ((size_t)e * H + n0) * II;
    const int NCH = II / BK;   // 16

    // ---- producer geometry ----
    // A (fp16): 64 rows x 8 segs = 512 tasks, 2/thread
    const __half* srcA[2];
    int aoff[2];
    #pragma unroll
    for (int j = 0; j < 2; j++) {
        const int idx = tid + j * 256, ra = idx >> 3, sg = idx & 7;
        srcA[j] = g_act + (size_t)srow[ra] * II + sg * 8;
        aoff[j] = ra * PADK + sg * 8;
    }
    // B (fp32): 128 rows x 16 float4 segs = 2048 tasks, 8/thread
    const float* srcB[8];
    int boff[8];
    #pragma unroll
    for (int j = 0; j < 8; j++) {
        const int idx = tid + j * 256, r = idx >> 4, c = idx & 15;
        srcB[j] = WdE + (size_t)r * II + c * 4;
        boff[j] = r * PADK + c * 4;
    }

    const int wm = wid >> 2;   // 0..1
    const int wn = wid & 3;    // 0..3
    const uint32_t offA0 = (uint32_t)((wm * 32 + (lane & 15)) * PADK + ((lane >> 4) << 3));
    const uint32_t offA1 = offA0 + 16 * PADK;
    const uint32_t offB0 = (uint32_t)((wn * 32 + ((lane >> 4) << 3) + (lane & 7)) * PADK
                                      + (((lane >> 3) & 1) << 3));
    const uint32_t offB1 = offB0 + 16 * PADK;

    float acc[2][4][4] = {};
    uint4  pa[2];
    float4 pb[8];

    {
        #pragma unroll
        for (int j = 0; j < 2; j++) pa[j] = *(const uint4*)srcA[j];
        #pragma unroll
        for (int j = 0; j < 8; j++) pb[j] = *(const float4*)srcB[j];
        #pragma unroll
        for (int j = 0; j < 2; j++) *(uint4*)(sm + DA + aoff[j]) = pa[j];
        #pragma unroll
        for (int j = 0; j < 8; j++) *(uint2*)(sm + DB + boff[j]) = cvt4_f16(pb[j]);
        __syncthreads();
    }

    for (int ch = 0; ch < NCH; ch++) {
        if (ch + 1 < NCH) {
            const int k0 = (ch + 1) * BK;
            #pragma unroll
            for (int j = 0; j < 2; j++) pa[j] = *(const uint4*)(srcA[j] + k0);
            #pragma unroll
            for (int j = 0; j < 8; j++) pb[j] = *(const float4*)(srcB[j] + k0);
        }

        {
            const uint32_t sbase = smem_u32(sm + (ch & 1) * STG_ELEMS);
            #pragma unroll
            for (int k16 = 0; k16 < BK; k16 += 16) {
                const uint32_t kb = (uint32_t)k16 * 2;
                uint32_t ah[2][4];
                ldm_x4(ah[0], sbase + (DA * 2) + (offA0 * 2) + kb);
                ldm_x4(ah[1], sbase + (DA * 2) + (offA1 * 2) + kb);
                uint32_t bv[2][4];
                ldm_x4(bv[0], sbase + (DB * 2) + (offB0 * 2) + kb);
                ldm_x4(bv[1], sbase + (DB * 2) + (offB1 * 2) + kb);
                #pragma unroll
                for (int mt = 0; mt < 2; mt++) {
                    #pragma unroll
                    for (int nt = 0; nt < 4; nt++) {
                        const int p = nt >> 1, q = (nt & 1) * 2;
                        mma_f16(acc[mt][nt], ah[mt], bv[p][q], bv[p][q + 1]);
                    }
                }
            }
        }

        if (ch + 1 < NCH) {
            __half* s = sm + ((ch + 1) & 1) * STG_ELEMS;
            #pragma unroll
            for (int j = 0; j < 2; j++) *(uint4*)(s + DA + aoff[j]) = pa[j];
            #pragma unroll
            for (int j = 0; j < 8; j++) *(uint2*)(s + DB + boff[j]) = cvt4_f16(pb[j]);
        }
        __syncthreads();
    }

    // epilogue: atomic scatter into out
    #pragma unroll
    for (int mt = 0; mt < 2; mt++) {
        #pragma unroll
        for (int nt = 0; nt < 4; nt++) {
            const int c  = n0 + wn * 32 + nt * 8 + (lane & 3) * 2;
            const int r0 = wm * 32 + mt * 16 + (lane >> 2);
            #pragma unroll
            for (int hf = 0; hf < 2; hf++) {
                const int r = r0 + hf * 8;
                if (m0 + r < cnt) {
                    float* orow = out + (size_t)stok[r] * H + c;
                    atomicAdd(&orow[0], acc[mt][nt][hf * 2 + 0]);
                    atomicAdd(&orow[1], acc[mt][nt][hf * 2 + 1]);
                }
            }
        }
    }
}

// ======================= launch =======================
extern "C" void kernel_launch(void* const* d_in, const int* in_sizes, int n_in,
                              void* d_out, int out_size)
{
    const float* x     = (const float*)d_in[0];
    const float* Wg    = (const float*)d_in[1];
    const float* Wu    = (const float*)d_in[2];
    const float* Wd    = (const float*)d_in[3];
    const float* Wgate = (const float*)d_in[4];
    float* out = (float*)d_out;

    cudaFuncSetAttribute(gateup_mma, cudaFuncAttributeMaxDynamicSharedMemorySize, SMEM_DYN);
    cudaFuncSetAttribute(down_mma,   cudaFuncAttributeMaxDynamicSharedMemorySize, SMEM_DYN);

    void* cnt_ptr = nullptr;
    cudaGetSymbolAddress(&cnt_ptr, g_cnt);
    cudaMemsetAsync(cnt_ptr, 0, E * sizeof(int));
    cudaMemsetAsync(d_out, 0, (size_t)T * H * sizeof(float));

    xhalf_kernel<<<(T * H / 4) / 256, 256>>>(x);
    gate_kernel<<<T, 256>>>(x, Wgate);
    scan_kernel<<<1, 32>>>();

    dim3 g1(II / 64, T / BM, E);     // 16 x 8 x 64
    gateup_mma<<<g1, 256, SMEM_DYN>>>(Wg, Wu);

    dim3 g2(H / 128, T / BM, E);     // 16 x 8 x 64
    down_mma<<<g2, 256, SMEM_DYN>>>(Wd, out);
}